// round 8
// baseline (speedup 1.0000x reference)
#include <cuda_runtime.h>
#include <math.h>

// ---------------- constants ----------------
#define NB 16
#define C1 64
#define H1 256
#define HP 128
#define CH 704
#define NP 23
#define PI_D 3.14159265358979323846

typedef unsigned long long u64;

// packed fp32x2 helpers (SASS FFMA2 — 2x fp32 FMA per issue, IEEE-exact per lane)
__device__ __forceinline__ u64 ffma2(u64 a, u64 b, u64 c) {
    u64 d;
    asm("fma.rn.f32x2 %0, %1, %2, %3;" : "=l"(d) : "l"(a), "l"(b), "l"(c));
    return d;
}
__device__ __forceinline__ u64 pack2(float x, float y) {
    u64 d;
    asm("mov.b64 %0, {%1, %2};" : "=l"(d) : "f"(x), "f"(y));
    return d;
}
__device__ __forceinline__ void unpack2(u64 v, float& x, float& y) {
    asm("mov.b64 {%0, %1}, %2;" : "=f"(x), "=f"(y) : "l"(v));
}

// ---------------- device scratch ----------------
__device__ float g_conv0[(size_t)NB*C1*H1*H1];       // 256 MB
__device__ float g_f   [(size_t)NB*C1*HP*HP];        // 64 MB
__device__ float g_xt1 [(size_t)NB*C1*HP*HP];
__device__ float g_xt2 [(size_t)NB*C1*HP*HP];
__device__ float g_h   [(size_t)NB*CH*NP*NP];
__device__ float g_c1p [(size_t)8*NB*64*441];
__device__ float g_c1  [(size_t)NB*64*441];
__device__ float g_p1  [(size_t)NB*64*100];
__device__ float g_c2  [(size_t)NB*32*64];
__device__ float g_fc1 [(size_t)NB*128];
__device__ float g_bn0row[2*64*4096];                // [sum/sq][ch][block]
__device__ float g_scale0[64], g_shift0[64];
__device__ float g_scale1[64], g_shift1[64];

// ---------------- stem conv: 7x7 s2 p3, 3->64 ch, FFMA2 ----------------
// block = one output row (256 px), 256 threads.
// thread: half = t>>7 selects channels [32h,32h+32); tt = t&127 -> pixels (2tt, 2tt+1).
// Also emits per-block bn partial sums/sumsq (deterministic tree).
__global__ __launch_bounds__(256) void stem_kernel(const float* __restrict__ x,
                                                   const float* __restrict__ w) {
    __shared__ __align__(16) float smem_buf[9408];   // weights [idx][64]; reused as red[64][129]
    float* ws = smem_buf;
    int b = blockIdx.y, oh = blockIdx.x;
    int t = threadIdx.x;
    for (int i = t; i < 9408; i += 256) {
        int co = i / 147, idx = i % 147;
        ws[idx*64 + co] = w[i];
    }
    __syncthreads();
    int half = t >> 7, tt = t & 127;
    u64 acc0[16], acc1[16];              // acc[k] = local channel pair (2k,2k+1); pix0 / pix1
#pragma unroll
    for (int i = 0; i < 16; i++) { acc0[i] = 0ull; acc1[i] = 0ull; }
#pragma unroll 1
    for (int c = 0; c < 3; c++) {
#pragma unroll 1
        for (int kh = 0; kh < 7; kh++) {
            int ih = oh*2 - 3 + kh;
            bool vrow = ((unsigned)ih < 512u);
            const float* xrow = x + (((size_t)b*512 + ih)*512)*3 + c;
#pragma unroll
            for (int kw = 0; kw < 7; kw++) {
                int iw0 = 4*tt - 3 + kw;
                float v0 = (vrow && (unsigned)iw0 < 512u) ? xrow[(size_t)iw0*3] : 0.f;
                float v1 = (vrow && (unsigned)(iw0+2) < 512u) ? xrow[(size_t)(iw0+2)*3] : 0.f;
                u64 pv0 = pack2(v0, v0);
                u64 pv1 = pack2(v1, v1);
                int idx = (c*7 + kh)*7 + kw;
                const ulonglong2* wp = (const ulonglong2*)(ws + idx*64 + half*32);
#pragma unroll
                for (int g = 0; g < 8; g++) {
                    ulonglong2 q = wp[g];
                    acc0[2*g  ] = ffma2(pv0, q.x, acc0[2*g  ]);
                    acc0[2*g+1] = ffma2(pv0, q.y, acc0[2*g+1]);
                    acc1[2*g  ] = ffma2(pv1, q.x, acc1[2*g  ]);
                    acc1[2*g+1] = ffma2(pv1, q.y, acc1[2*g+1]);
                }
            }
        }
    }
    // store conv output: per channel float2 (pix0, pix1) — coalesced
    size_t base = ((size_t)(b*64 + half*32))*65536 + (size_t)oh*256 + 2*tt;
#pragma unroll
    for (int k = 0; k < 16; k++) {
        float l0, h0, l1, h1;
        unpack2(acc0[k], l0, h0);
        unpack2(acc1[k], l1, h1);
        *(float2*)(g_conv0 + base + (size_t)(2*k  )*65536) = make_float2(l0, l1);
        *(float2*)(g_conv0 + base + (size_t)(2*k+1)*65536) = make_float2(h0, h1);
    }
    // ---- bn partial stats over this row (deterministic) ----
    int blk = b*256 + oh;
    float* red = smem_buf;               // [64][129]
    int rc = t >> 2, rq = t & 3;
    // pass 1: sums
    __syncthreads();
#pragma unroll
    for (int k = 0; k < 16; k++) {
        float l0, h0, l1, h1;
        unpack2(acc0[k], l0, h0);
        unpack2(acc1[k], l1, h1);
        red[(half*32 + 2*k  )*129 + tt] = l0 + l1;
        red[(half*32 + 2*k+1)*129 + tt] = h0 + h1;
    }
    __syncthreads();
    {
        float s = 0.f;
#pragma unroll
        for (int i = 0; i < 32; i++) s += red[rc*129 + rq*32 + i];
        s += __shfl_xor_sync(0xffffffffu, s, 1);
        s += __shfl_xor_sync(0xffffffffu, s, 2);
        if (rq == 0) g_bn0row[rc*4096 + blk] = s;
    }
    __syncthreads();
    // pass 2: sums of squares
#pragma unroll
    for (int k = 0; k < 16; k++) {
        float l0, h0, l1, h1;
        unpack2(acc0[k], l0, h0);
        unpack2(acc1[k], l1, h1);
        red[(half*32 + 2*k  )*129 + tt] = l0*l0 + l1*l1;
        red[(half*32 + 2*k+1)*129 + tt] = h0*h0 + h1*h1;
    }
    __syncthreads();
    {
        float s = 0.f;
#pragma unroll
        for (int i = 0; i < 32; i++) s += red[rc*129 + rq*32 + i];
        s += __shfl_xor_sync(0xffffffffu, s, 1);
        s += __shfl_xor_sync(0xffffffffu, s, 2);
        if (rq == 0) g_bn0row[(64 + rc)*4096 + blk] = s;
    }
}

// ---------------- bn0 final: reduce 4096 row-partials per channel ----------------
__global__ void bn0_final(const float* __restrict__ g, const float* __restrict__ bb) {
    int c = blockIdx.x;
    float s = 0.f, q = 0.f;
    for (int i = threadIdx.x; i < 4096; i += 256) {
        s += g_bn0row[c*4096 + i];
        q += g_bn0row[(64 + c)*4096 + i];
    }
    __shared__ float rs[256], rq[256];
    rs[threadIdx.x] = s; rq[threadIdx.x] = q; __syncthreads();
    for (int st = 128; st > 0; st >>= 1) {
        if (threadIdx.x < st) { rs[threadIdx.x] += rs[threadIdx.x+st]; rq[threadIdx.x] += rq[threadIdx.x+st]; }
        __syncthreads();
    }
    if (threadIdx.x == 0) {
        const float inv = 1.f / 1048576.f;
        float m = rs[0]*inv, var = rq[0]*inv - m*m;
        float sc = g[c] * rsqrtf(var + 1e-5f);
        g_scale0[c] = sc; g_shift0[c] = bb[c] - m*sc;
    }
}

// ---------------- fused bn+relu+maxpool 3x3 s2 p1, 2 outputs/thread ----------------
__global__ void pool0() {
    int idx = blockIdx.x*256 + threadIdx.x;          // 16*64*128*64
    int owp = idx & 63, oh = (idx >> 6) & 127, c = (idx >> 13) & 63, b = idx >> 19;
    float sc = g_scale0[c], sh = g_shift0[c];
    const float* src = g_conv0 + ((size_t)(b*64 + c))*65536;
    float mx0 = -3.4e38f, mn0 = 3.4e38f, mx1 = -3.4e38f, mn1 = 3.4e38f;
    int c0 = 4*owp;
#pragma unroll
    for (int dy = 0; dy < 3; dy++) {
        int ih = oh*2 - 1 + dy;
        if ((unsigned)ih >= 256u) continue;
        const float* r = src + ih*256;
        float4 qv = *(const float4*)(r + c0);
        if (owp > 0) {
            float left = r[c0 - 1];
            mx0 = fmaxf(mx0, left); mn0 = fminf(mn0, left);
        }
        mx0 = fmaxf(mx0, fmaxf(qv.x, qv.y));
        mn0 = fminf(mn0, fminf(qv.x, qv.y));
        mx1 = fmaxf(mx1, fmaxf(qv.y, fmaxf(qv.z, qv.w)));
        mn1 = fminf(mn1, fminf(qv.y, fminf(qv.z, qv.w)));
    }
    float v0 = (sc >= 0.f) ? sc*mx0 + sh : sc*mn0 + sh;
    float v1 = (sc >= 0.f) ? sc*mx1 + sh : sc*mn1 + sh;
    size_t obase = ((size_t)(b*64 + c))*16384 + (size_t)oh*128 + 2*owp;
    *(float2*)(g_f + obase) = make_float2(fmaxf(v0, 0.f), fmaxf(v1, 0.f));
}

// ---------------- grid_sample, both thetas, 2 px/thread, unrolled c-loop ----------------
__global__ __launch_bounds__(128) void gridsample_kernel(
        float p00, float p01, float p02, float p10, float p11, float p12,
        float q00, float q01, float q02, float q10, float q11, float q12) {
    int t = threadIdx.x;
    int hh = blockIdx.x*2 + (t >> 6);
    int w0 = 2*(t & 63);
    int b = blockIdx.y, which = blockIdx.z;
    float t00 = which ? q00 : p00, t01 = which ? q01 : p01, t02 = which ? q02 : p02;
    float t10 = which ? q10 : p10, t11 = which ? q11 : p11, t12 = which ? q12 : p12;
    float* out = which ? g_xt2 : g_xt1;
    int offA[2][4]; float wfA[2][4];
#pragma unroll
    for (int px = 0; px < 2; px++) {
        int w = w0 + px;
        float gx = (float)(2*w + 1) * (1.f/128.f) - 1.f;
        float gy = (float)(2*hh + 1) * (1.f/128.f) - 1.f;
        float grx = gx*t00 + gy*t01 + t02;
        float gry = gx*t10 + gy*t11 + t12;
        float ix = ((grx + 1.f)*128.f - 1.f)*0.5f;
        float iy = ((gry + 1.f)*128.f - 1.f)*0.5f;
        float x0f = floorf(ix), y0f = floorf(iy);
        int x0 = (int)x0f, y0 = (int)y0f;
        float wa = (x0f + 1.f - ix)*(y0f + 1.f - iy);
        float wb = (x0f + 1.f - ix)*(iy - y0f);
        float wc = (ix - x0f)*(y0f + 1.f - iy);
        float wd = (ix - x0f)*(iy - y0f);
        float wt[4] = {wa, wb, wc, wd};
        int xs2[2] = {x0, x0 + 1}, ys2[2] = {y0, y0 + 1};
#pragma unroll
        for (int dx = 0; dx < 2; dx++)
#pragma unroll
            for (int dy = 0; dy < 2; dy++) {
                int xx = xs2[dx], yy = ys2[dy];
                bool valid = ((unsigned)xx < 128u) && ((unsigned)yy < 128u);
                int xc = min(max(xx, 0), 127), yc = min(max(yy, 0), 127);
                int k = dx*2 + dy;
                offA[px][k] = yc*128 + xc;
                wfA[px][k] = valid ? wt[k] : 0.f;
            }
    }
    size_t base = ((size_t)b*64)*16384;
    int pix = hh*128 + w0;
    const float* src = g_f + base;
#pragma unroll 4
    for (int c = 0; c < 64; c++) {
        const float* sp = src + c*16384;
        float r0 = sp[offA[0][0]]*wfA[0][0] + sp[offA[0][1]]*wfA[0][1]
                 + sp[offA[0][2]]*wfA[0][2] + sp[offA[0][3]]*wfA[0][3];
        float r1 = sp[offA[1][0]]*wfA[1][0] + sp[offA[1][1]]*wfA[1][1]
                 + sp[offA[1][2]]*wfA[1][2] + sp[offA[1][3]]*wfA[1][3];
        *(float2*)(out + base + (size_t)c*16384 + pix) = make_float2(r0, r1);
    }
}

// ---------------- roialign: 4-way channel split, writes into concat g_h ----------------
__global__ void roialign_kernel(const float* __restrict__ box) {
    int blk = blockIdx.x;            // 16*11
    int cq  = blockIdx.y;            // 0..3 -> channels [16cq, 16cq+16)
    int b = blk / 11, s = blk % 11;
    const float* feat; int r;
    if (s < 7)       { feat = g_f;   r = s;     }
    else if (s < 9)  { feat = g_xt1; r = s - 7; }
    else             { feat = g_xt2; r = s - 9; }
    const float* bx = box + b*28 + r*4;
    float rx1 = bx[0]*0.25f, ry1 = bx[1]*0.25f, rx2 = bx[2]*0.25f, ry2 = bx[3]*0.25f;
    float bw = fmaxf(rx2 - rx1, 1.f) * (1.f/23.f);
    float bh = fmaxf(ry2 - ry1, 1.f) * (1.f/23.f);
    __shared__ int   sy0[46], sy1[46], sx0[46], sx1[46];
    __shared__ float sly[46], slx[46];
    __shared__ int   sey[46], sex[46];
    int t = threadIdx.x;
    if (t < 46) {
        float pos = (float)(t >> 1) + 0.25f + 0.5f*(float)(t & 1);
        float yv = ry1 + pos*bh;
        sey[t] = (yv < -1.f) || (yv > 128.f);
        float y = fminf(fmaxf(yv, 0.f), 127.f);
        float y0f = floorf(y); int y0 = (int)y0f;
        sy0[t] = y0; sy1[t] = min(y0 + 1, 127); sly[t] = y - y0f;
        float xv = rx1 + pos*bw;
        sex[t] = (xv < -1.f) || (xv > 128.f);
        float xx = fminf(fmaxf(xv, 0.f), 127.f);
        float x0f = floorf(xx); int x0 = (int)x0f;
        sx0[t] = x0; sx1[t] = min(x0 + 1, 127); slx[t] = xx - x0f;
    }
    __syncthreads();
    const float* fb = feat + ((size_t)b*64)*16384;
    float* ob = g_h + ((size_t)(b*704 + s*64))*529;
    for (int o = t; o < 16*529; o += 256) {
        int c = cq*16 + o / 529, pp = o % 529;
        int py = pp / 23, px = pp % 23;
        const float* img = fb + (size_t)c*16384;
        float acc = 0.f;
#pragma unroll
        for (int dy = 0; dy < 2; dy++) {
            int jy = py*2 + dy;
            int yy0 = sy0[jy], yy1 = sy1[jy];
            float ly = sly[jy], hy = 1.f - ly;
            int ey = sey[jy];
#pragma unroll
            for (int dx = 0; dx < 2; dx++) {
                int jx = px*2 + dx;
                int xx0 = sx0[jx], xx1 = sx1[jx];
                float lx = slx[jx], hx = 1.f - lx;
                float v = img[yy0*128 + xx0]*(hy*hx) + img[yy0*128 + xx1]*(hy*lx)
                        + img[yy1*128 + xx0]*(ly*hx) + img[yy1*128 + xx1]*(ly*lx);
                if (ey || sex[jx]) v = 0.f;
                acc += v;
            }
        }
        ob[(size_t)c*529 + pp] = acc * 0.25f;
    }
}

// ---------------- conv1 3x3 valid, 704->64, FFMA2, ci-split partials (R3-proven) ----------------
__global__ __launch_bounds__(448) void conv1_kernel(const float* __restrict__ w) {
    int split = blockIdx.x;   // 0..7 (88 ci each)
    int cog   = blockIdx.y;   // 0..1 (32 couts each)
    int b     = blockIdx.z;
    __shared__ __align__(16) float tile[532];
    __shared__ __align__(16) float ws[288];          // [k][j], j = co_local 0..31
    int t = threadIdx.x;
    int oh = t / 21, ow = t % 21;
    bool active = (t < 441);
    u64 acc[16];
#pragma unroll
    for (int i = 0; i < 16; i++) acc[i] = 0ull;
    int ci0 = split*88;
    for (int ci = ci0; ci < ci0 + 88; ci++) {
        __syncthreads();
        for (int i = t; i < 529; i += 448)
            tile[i] = g_h[((size_t)(b*704 + ci))*529 + i];
        if (t < 288) {
            int j = t / 9, k = t % 9;
            ws[k*32 + j] = w[((size_t)(cog*32 + j)*704 + ci)*9 + k];
        }
        __syncthreads();
        if (active) {
            float r[9];
#pragma unroll
            for (int kh = 0; kh < 3; kh++)
#pragma unroll
                for (int kw = 0; kw < 3; kw++)
                    r[kh*3 + kw] = tile[(oh + kh)*23 + ow + kw];
#pragma unroll
            for (int k = 0; k < 9; k++) {
                u64 pv = pack2(r[k], r[k]);
                const ulonglong2* w2 = (const ulonglong2*)(ws + k*32);
#pragma unroll
                for (int g = 0; g < 8; g++) {
                    ulonglong2 q = w2[g];
                    acc[2*g  ] = ffma2(pv, q.x, acc[2*g  ]);
                    acc[2*g+1] = ffma2(pv, q.y, acc[2*g+1]);
                }
            }
        }
    }
    if (active) {
#pragma unroll
        for (int k = 0; k < 16; k++) {
            float lo, hi;
            unpack2(acc[k], lo, hi);
            int co = cog*32 + 2*k;
            g_c1p[(((size_t)split*16 + b)*64 + co    )*441 + t] = lo;
            g_c1p[(((size_t)split*16 + b)*64 + co + 1)*441 + t] = hi;
        }
    }
}

__global__ void conv1_reduce() {
    int o = blockIdx.x*256 + threadIdx.x;
    if (o >= 16*64*441) return;
    float s = 0.f;
#pragma unroll
    for (int k = 0; k < 8; k++) s += g_c1p[(size_t)k*16*64*441 + o];
    g_c1[o] = s;
}

// ---------------- bn1 stats ----------------
__global__ void bn1_stats(const float* __restrict__ g, const float* __restrict__ bb) {
    int c = blockIdx.x;
    float s = 0.f, q = 0.f;
    for (int i = threadIdx.x; i < 16*441; i += 256) {
        int b = i / 441, t = i % 441;
        float v = g_c1[((size_t)(b*64 + c))*441 + t];
        s += v; q += v*v;
    }
    __shared__ float rs[256], rq[256];
    rs[threadIdx.x] = s; rq[threadIdx.x] = q; __syncthreads();
    for (int st = 128; st > 0; st >>= 1) {
        if (threadIdx.x < st) { rs[threadIdx.x] += rs[threadIdx.x+st]; rq[threadIdx.x] += rq[threadIdx.x+st]; }
        __syncthreads();
    }
    if (threadIdx.x == 0) {
        const float inv = 1.f / 7056.f;
        float m = rs[0]*inv, var = rq[0]*inv - m*m;
        float sc = g[c] * rsqrtf(var + 1e-5f);
        g_scale1[c] = sc; g_shift1[c] = bb[c] - m*sc;
    }
}

// ---------------- bn1+relu+maxpool2x2 ----------------
__global__ void pool1() {
    int idx = blockIdx.x*256 + threadIdx.x;   // 16*64*100
    if (idx >= 102400) return;
    int ow = idx % 10, oh = (idx/10) % 10, c = (idx/100) % 64, b = idx/6400;
    float sc = g_scale1[c], sh = g_shift1[c];
    const float* src = g_c1 + ((size_t)(b*64 + c))*441;
    float m = 0.f;
#pragma unroll
    for (int dy = 0; dy < 2; dy++)
#pragma unroll
        for (int dx = 0; dx < 2; dx++)
            m = fmaxf(m, fmaxf(sc*src[(oh*2 + dy)*21 + ow*2 + dx] + sh, 0.f));
    g_p1[idx] = m;
}

// ---------------- conv2 3x3 valid, 64->32, +bias, relu ----------------
__global__ void conv2_kernel(const float* __restrict__ w, const float* __restrict__ bias) {
    int idx = blockIdx.x*256 + threadIdx.x;   // 16*32*64
    int ow = idx & 7, oh = (idx >> 3) & 7, co = (idx >> 6) & 31, b = idx >> 11;
    const float* src = g_p1 + (size_t)b*6400;
    const float* wp  = w + (size_t)co*576;
    float acc = bias[co];
    for (int ci = 0; ci < 64; ci++) {
        const float* sp = src + ci*100;
        const float* wc = wp + ci*9;
#pragma unroll
        for (int kh = 0; kh < 3; kh++)
#pragma unroll
            for (int kw = 0; kw < 3; kw++)
                acc += sp[(oh + kh)*10 + ow + kw] * wc[kh*3 + kw];
    }
    g_c2[idx] = fmaxf(acc, 0.f);
}

// ---------------- fc1 + relu ----------------
__global__ __launch_bounds__(128) void fc1_kernel(const float* __restrict__ w, const float* __restrict__ bias) {
    int b = blockIdx.x, j = threadIdx.x;
    __shared__ __align__(16) float xv[2048];
    for (int i = j; i < 2048; i += 128) xv[i] = g_c2[(size_t)b*2048 + i];
    __syncthreads();
    const float4* wp = (const float4*)(w + (size_t)j*2048);
    const float4* xp = (const float4*)xv;
    float acc = 0.f;
#pragma unroll 4
    for (int k = 0; k < 512; k++) {
        float4 wv = wp[k], x4 = xp[k];
        acc += wv.x*x4.x + wv.y*x4.y + wv.z*x4.z + wv.w*x4.w;
    }
    g_fc1[b*128 + j] = fmaxf(acc + bias[j], 0.f);
}

// ---------------- head + tanh ----------------
__global__ void head_kernel(const float* __restrict__ w, const float* __restrict__ bias,
                            float* __restrict__ out) {
    int t = threadIdx.x; if (t >= 192) return;
    int b = t / 12, j = t % 12;
    const float* wp = w + j*128;
    const float* xp = g_fc1 + b*128;
    float acc = bias[j];
#pragma unroll 4
    for (int k = 0; k < 128; k++) acc += wp[k]*xp[k];
    out[b*12 + j] = tanhf(acc);
}

// ---------------- launch ----------------
extern "C" void kernel_launch(void* const* d_in, const int* in_sizes, int n_in,
                              void* d_out, int out_size) {
    const float* x       = (const float*)d_in[0];
    const float* box     = (const float*)d_in[1];
    const float* stem_w  = (const float*)d_in[2];
    const float* stem_g  = (const float*)d_in[3];
    const float* stem_b  = (const float*)d_in[4];
    const float* conv1_w = (const float*)d_in[5];
    /* conv1_b (d_in[6]) cancels under batchnorm's mean subtraction */
    const float* bn1_g   = (const float*)d_in[7];
    const float* bn1_b   = (const float*)d_in[8];
    const float* conv2_w = (const float*)d_in[9];
    const float* conv2_b = (const float*)d_in[10];
    const float* fc1_w   = (const float*)d_in[11];
    const float* fc1_b   = (const float*)d_in[12];
    const float* head_w  = (const float*)d_in[13];
    const float* head_b  = (const float*)d_in[14];
    float* out = (float*)d_out;

    stem_kernel<<<dim3(256, 16), 256>>>(x, stem_w);
    bn0_final<<<64, 256>>>(stem_g, stem_b);
    pool0<<<32768, 256>>>();

    double a1 = -5.0*PI_D/180.0, a2 = 5.0*PI_D/180.0;
    gridsample_kernel<<<dim3(64, 16, 2), 128>>>(
        (float)cos(a1), (float)sin(-a1), 0.f, (float)sin(a1), (float)cos(a1), 0.f,
        (float)cos(a2), (float)sin(-a2), 0.f, (float)sin(a2), (float)cos(a2), 0.f);

    roialign_kernel<<<dim3(176, 4), 256>>>(box);

    conv1_kernel<<<dim3(8, 2, 16), 448>>>(conv1_w);
    conv1_reduce<<<1764, 256>>>();
    bn1_stats<<<64, 256>>>(bn1_g, bn1_b);
    pool1<<<400, 256>>>();
    conv2_kernel<<<128, 256>>>(conv2_w, conv2_b);
    fc1_kernel<<<16, 128>>>(fc1_w, fc1_b);
    head_kernel<<<1, 256>>>(head_w, head_b, out);
}

// round 9
// speedup vs baseline: 1.0068x; 1.0068x over previous
#include <cuda_runtime.h>
#include <math.h>

// ---------------- constants ----------------
#define NB 16
#define C1 64
#define H1 256
#define HP 128
#define CH 704
#define NP 23
#define PI_D 3.14159265358979323846

typedef unsigned long long u64;

// packed fp32x2 helpers (SASS FFMA2 — 2x fp32 FMA per issue, IEEE-exact per lane)
__device__ __forceinline__ u64 ffma2(u64 a, u64 b, u64 c) {
    u64 d;
    asm("fma.rn.f32x2 %0, %1, %2, %3;" : "=l"(d) : "l"(a), "l"(b), "l"(c));
    return d;
}
__device__ __forceinline__ u64 pack2(float x, float y) {
    u64 d;
    asm("mov.b64 %0, {%1, %2};" : "=l"(d) : "f"(x), "f"(y));
    return d;
}
__device__ __forceinline__ void unpack2(u64 v, float& x, float& y) {
    asm("mov.b64 {%0, %1}, %2;" : "=f"(x), "=f"(y) : "l"(v));
}

// ---------------- device scratch ----------------
__device__ float g_conv0[(size_t)NB*C1*H1*H1];       // 256 MB
__device__ float g_f   [(size_t)NB*C1*HP*HP];        // 64 MB
__device__ float g_xt1 [(size_t)NB*C1*HP*HP];
__device__ float g_xt2 [(size_t)NB*C1*HP*HP];
__device__ float g_h   [(size_t)NB*CH*NP*NP];
__device__ float g_c1p [(size_t)8*NB*64*441];
__device__ float g_c1  [(size_t)NB*64*441];
__device__ float g_p1  [(size_t)NB*64*100];
__device__ float g_c2  [(size_t)NB*32*64];
__device__ float g_fc1 [(size_t)NB*128];
__device__ float g_bn0row[2*64*4096];                // [sum/sq][ch][block]
__device__ float g_scale0[64], g_shift0[64];
__device__ float g_scale1[64], g_shift1[64];
__device__ float g_probe[4];

// ---------------- probe kernels (shift stem into ncu's 4th-launch capture slot) ----------------
__global__ void probe0() { if (threadIdx.x == 0) g_probe[0] = 0.f; }
__global__ void probe1() { if (threadIdx.x == 0) g_probe[1] = 0.f; }
__global__ void probe2() { if (threadIdx.x == 0) g_probe[2] = 0.f; }

// ---------------- stem conv: 7x7 s2 p3, 3->64 ch, FFMA2 ----------------
// block = one output row (256 px), 256 threads.
// thread: half = t>>7 selects channels [32h,32h+32); tt = t&127 -> pixels (2tt, 2tt+1).
// Also emits per-block bn partial sums/sumsq (deterministic tree).
__global__ __launch_bounds__(256) void stem_kernel(const float* __restrict__ x,
                                                   const float* __restrict__ w) {
    __shared__ __align__(16) float smem_buf[9408];   // weights [idx][64]; reused as red[64][129]
    float* ws = smem_buf;
    int b = blockIdx.y, oh = blockIdx.x;
    int t = threadIdx.x;
    for (int i = t; i < 9408; i += 256) {
        int co = i / 147, idx = i % 147;
        ws[idx*64 + co] = w[i];
    }
    __syncthreads();
    int half = t >> 7, tt = t & 127;
    u64 acc0[16], acc1[16];              // acc[k] = local channel pair (2k,2k+1); pix0 / pix1
#pragma unroll
    for (int i = 0; i < 16; i++) { acc0[i] = 0ull; acc1[i] = 0ull; }
#pragma unroll 1
    for (int c = 0; c < 3; c++) {
#pragma unroll 1
        for (int kh = 0; kh < 7; kh++) {
            int ih = oh*2 - 3 + kh;
            bool vrow = ((unsigned)ih < 512u);
            const float* xrow = x + (((size_t)b*512 + ih)*512)*3 + c;
#pragma unroll
            for (int kw = 0; kw < 7; kw++) {
                int iw0 = 4*tt - 3 + kw;
                float v0 = (vrow && (unsigned)iw0 < 512u) ? xrow[(size_t)iw0*3] : 0.f;
                float v1 = (vrow && (unsigned)(iw0+2) < 512u) ? xrow[(size_t)(iw0+2)*3] : 0.f;
                u64 pv0 = pack2(v0, v0);
                u64 pv1 = pack2(v1, v1);
                int idx = (c*7 + kh)*7 + kw;
                const ulonglong2* wp = (const ulonglong2*)(ws + idx*64 + half*32);
#pragma unroll
                for (int g = 0; g < 8; g++) {
                    ulonglong2 q = wp[g];
                    acc0[2*g  ] = ffma2(pv0, q.x, acc0[2*g  ]);
                    acc0[2*g+1] = ffma2(pv0, q.y, acc0[2*g+1]);
                    acc1[2*g  ] = ffma2(pv1, q.x, acc1[2*g  ]);
                    acc1[2*g+1] = ffma2(pv1, q.y, acc1[2*g+1]);
                }
            }
        }
    }
    // store conv output: per channel float2 (pix0, pix1) — coalesced
    size_t base = ((size_t)(b*64 + half*32))*65536 + (size_t)oh*256 + 2*tt;
#pragma unroll
    for (int k = 0; k < 16; k++) {
        float l0, h0, l1, h1;
        unpack2(acc0[k], l0, h0);
        unpack2(acc1[k], l1, h1);
        *(float2*)(g_conv0 + base + (size_t)(2*k  )*65536) = make_float2(l0, l1);
        *(float2*)(g_conv0 + base + (size_t)(2*k+1)*65536) = make_float2(h0, h1);
    }
    // ---- bn partial stats over this row (deterministic) ----
    int blk = b*256 + oh;
    float* red = smem_buf;               // [64][129]
    int rc = t >> 2, rq = t & 3;
    // pass 1: sums
    __syncthreads();
#pragma unroll
    for (int k = 0; k < 16; k++) {
        float l0, h0, l1, h1;
        unpack2(acc0[k], l0, h0);
        unpack2(acc1[k], l1, h1);
        red[(half*32 + 2*k  )*129 + tt] = l0 + l1;
        red[(half*32 + 2*k+1)*129 + tt] = h0 + h1;
    }
    __syncthreads();
    {
        float s = 0.f;
#pragma unroll
        for (int i = 0; i < 32; i++) s += red[rc*129 + rq*32 + i];
        s += __shfl_xor_sync(0xffffffffu, s, 1);
        s += __shfl_xor_sync(0xffffffffu, s, 2);
        if (rq == 0) g_bn0row[rc*4096 + blk] = s;
    }
    __syncthreads();
    // pass 2: sums of squares
#pragma unroll
    for (int k = 0; k < 16; k++) {
        float l0, h0, l1, h1;
        unpack2(acc0[k], l0, h0);
        unpack2(acc1[k], l1, h1);
        red[(half*32 + 2*k  )*129 + tt] = l0*l0 + l1*l1;
        red[(half*32 + 2*k+1)*129 + tt] = h0*h0 + h1*h1;
    }
    __syncthreads();
    {
        float s = 0.f;
#pragma unroll
        for (int i = 0; i < 32; i++) s += red[rc*129 + rq*32 + i];
        s += __shfl_xor_sync(0xffffffffu, s, 1);
        s += __shfl_xor_sync(0xffffffffu, s, 2);
        if (rq == 0) g_bn0row[(64 + rc)*4096 + blk] = s;
    }
}

// ---------------- bn0 final: reduce 4096 row-partials per channel ----------------
__global__ void bn0_final(const float* __restrict__ g, const float* __restrict__ bb) {
    int c = blockIdx.x;
    float s = 0.f, q = 0.f;
    for (int i = threadIdx.x; i < 4096; i += 256) {
        s += g_bn0row[c*4096 + i];
        q += g_bn0row[(64 + c)*4096 + i];
    }
    __shared__ float rs[256], rq[256];
    rs[threadIdx.x] = s; rq[threadIdx.x] = q; __syncthreads();
    for (int st = 128; st > 0; st >>= 1) {
        if (threadIdx.x < st) { rs[threadIdx.x] += rs[threadIdx.x+st]; rq[threadIdx.x] += rq[threadIdx.x+st]; }
        __syncthreads();
    }
    if (threadIdx.x == 0) {
        const float inv = 1.f / 1048576.f;
        float m = rs[0]*inv, var = rq[0]*inv - m*m;
        float sc = g[c] * rsqrtf(var + 1e-5f);
        g_scale0[c] = sc; g_shift0[c] = bb[c] - m*sc;
    }
}

// ---------------- fused bn+relu+maxpool 3x3 s2 p1, 2 outputs/thread ----------------
__global__ void pool0() {
    int idx = blockIdx.x*256 + threadIdx.x;          // 16*64*128*64
    int owp = idx & 63, oh = (idx >> 6) & 127, c = (idx >> 13) & 63, b = idx >> 19;
    float sc = g_scale0[c], sh = g_shift0[c];
    const float* src = g_conv0 + ((size_t)(b*64 + c))*65536;
    float mx0 = -3.4e38f, mn0 = 3.4e38f, mx1 = -3.4e38f, mn1 = 3.4e38f;
    int c0 = 4*owp;
#pragma unroll
    for (int dy = 0; dy < 3; dy++) {
        int ih = oh*2 - 1 + dy;
        if ((unsigned)ih >= 256u) continue;
        const float* r = src + ih*256;
        float4 qv = *(const float4*)(r + c0);
        if (owp > 0) {
            float left = r[c0 - 1];
            mx0 = fmaxf(mx0, left); mn0 = fminf(mn0, left);
        }
        mx0 = fmaxf(mx0, fmaxf(qv.x, qv.y));
        mn0 = fminf(mn0, fminf(qv.x, qv.y));
        mx1 = fmaxf(mx1, fmaxf(qv.y, fmaxf(qv.z, qv.w)));
        mn1 = fminf(mn1, fminf(qv.y, fminf(qv.z, qv.w)));
    }
    float v0 = (sc >= 0.f) ? sc*mx0 + sh : sc*mn0 + sh;
    float v1 = (sc >= 0.f) ? sc*mx1 + sh : sc*mn1 + sh;
    size_t obase = ((size_t)(b*64 + c))*16384 + (size_t)oh*128 + 2*owp;
    *(float2*)(g_f + obase) = make_float2(fmaxf(v0, 0.f), fmaxf(v1, 0.f));
}

// ---------------- grid_sample, both thetas in one launch (R3-proven, 1 px/thread) ----------------
__global__ void gridsample_kernel(float p00, float p01, float p02,
                                  float p10, float p11, float p12,
                                  float q00, float q01, float q02,
                                  float q10, float q11, float q12) {
    int w = threadIdx.x, hh = blockIdx.x, b = blockIdx.y, which = blockIdx.z;
    float t00 = which ? q00 : p00, t01 = which ? q01 : p01, t02 = which ? q02 : p02;
    float t10 = which ? q10 : p10, t11 = which ? q11 : p11, t12 = which ? q12 : p12;
    float* out = which ? g_xt2 : g_xt1;
    float gx = (float)(2*w + 1) * (1.f/128.f) - 1.f;
    float gy = (float)(2*hh + 1) * (1.f/128.f) - 1.f;
    float grx = gx*t00 + gy*t01 + t02;
    float gry = gx*t10 + gy*t11 + t12;
    float ix = ((grx + 1.f)*128.f - 1.f)*0.5f;
    float iy = ((gry + 1.f)*128.f - 1.f)*0.5f;
    float x0f = floorf(ix), y0f = floorf(iy);
    int x0 = (int)x0f, y0 = (int)y0f;
    float wa = (x0f + 1.f - ix)*(y0f + 1.f - iy);
    float wb = (x0f + 1.f - ix)*(iy - y0f);
    float wc = (ix - x0f)*(y0f + 1.f - iy);
    float wd = (ix - x0f)*(iy - y0f);
    int   off[4]; float wf[4];
    float wt[4] = {wa, wb, wc, wd};
    int xs2[2] = {x0, x0 + 1}, ys2[2] = {y0, y0 + 1};
#pragma unroll
    for (int dx = 0; dx < 2; dx++)
#pragma unroll
        for (int dy = 0; dy < 2; dy++) {
            int xx = xs2[dx], yy = ys2[dy];
            bool valid = ((unsigned)xx < 128u) && ((unsigned)yy < 128u);
            int xc = min(max(xx, 0), 127), yc = min(max(yy, 0), 127);
            int k = dx*2 + dy;
            off[k] = yc*128 + xc;
            wf[k] = valid ? wt[k] : 0.f;
        }
    size_t base = ((size_t)b*64)*16384;
    int pix = hh*128 + w;
    const float* src = g_f + base;
    for (int c = 0; c < 64; c++) {
        const float* sp = src + c*16384;
        out[base + (size_t)c*16384 + pix] =
            sp[off[0]]*wf[0] + sp[off[1]]*wf[1] + sp[off[2]]*wf[2] + sp[off[3]]*wf[3];
    }
}

// ---------------- roialign: 4-way channel split, writes into concat g_h ----------------
__global__ void roialign_kernel(const float* __restrict__ box) {
    int blk = blockIdx.x;            // 16*11
    int cq  = blockIdx.y;            // 0..3 -> channels [16cq, 16cq+16)
    int b = blk / 11, s = blk % 11;
    const float* feat; int r;
    if (s < 7)       { feat = g_f;   r = s;     }
    else if (s < 9)  { feat = g_xt1; r = s - 7; }
    else             { feat = g_xt2; r = s - 9; }
    const float* bx = box + b*28 + r*4;
    float rx1 = bx[0]*0.25f, ry1 = bx[1]*0.25f, rx2 = bx[2]*0.25f, ry2 = bx[3]*0.25f;
    float bw = fmaxf(rx2 - rx1, 1.f) * (1.f/23.f);
    float bh = fmaxf(ry2 - ry1, 1.f) * (1.f/23.f);
    __shared__ int   sy0[46], sy1[46], sx0[46], sx1[46];
    __shared__ float sly[46], slx[46];
    __shared__ int   sey[46], sex[46];
    int t = threadIdx.x;
    if (t < 46) {
        float pos = (float)(t >> 1) + 0.25f + 0.5f*(float)(t & 1);
        float yv = ry1 + pos*bh;
        sey[t] = (yv < -1.f) || (yv > 128.f);
        float y = fminf(fmaxf(yv, 0.f), 127.f);
        float y0f = floorf(y); int y0 = (int)y0f;
        sy0[t] = y0; sy1[t] = min(y0 + 1, 127); sly[t] = y - y0f;
        float xv = rx1 + pos*bw;
        sex[t] = (xv < -1.f) || (xv > 128.f);
        float xx = fminf(fmaxf(xv, 0.f), 127.f);
        float x0f = floorf(xx); int x0 = (int)x0f;
        sx0[t] = x0; sx1[t] = min(x0 + 1, 127); slx[t] = xx - x0f;
    }
    __syncthreads();
    const float* fb = feat + ((size_t)b*64)*16384;
    float* ob = g_h + ((size_t)(b*704 + s*64))*529;
    for (int o = t; o < 16*529; o += 256) {
        int c = cq*16 + o / 529, pp = o % 529;
        int py = pp / 23, px = pp % 23;
        const float* img = fb + (size_t)c*16384;
        float acc = 0.f;
#pragma unroll
        for (int dy = 0; dy < 2; dy++) {
            int jy = py*2 + dy;
            int yy0 = sy0[jy], yy1 = sy1[jy];
            float ly = sly[jy], hy = 1.f - ly;
            int ey = sey[jy];
#pragma unroll
            for (int dx = 0; dx < 2; dx++) {
                int jx = px*2 + dx;
                int xx0 = sx0[jx], xx1 = sx1[jx];
                float lx = slx[jx], hx = 1.f - lx;
                float v = img[yy0*128 + xx0]*(hy*hx) + img[yy0*128 + xx1]*(hy*lx)
                        + img[yy1*128 + xx0]*(ly*hx) + img[yy1*128 + xx1]*(ly*lx);
                if (ey || sex[jx]) v = 0.f;
                acc += v;
            }
        }
        ob[(size_t)c*529 + pp] = acc * 0.25f;
    }
}

// ---------------- conv1 3x3 valid, 704->64, FFMA2, ci-split partials (R3-proven) ----------------
__global__ __launch_bounds__(448) void conv1_kernel(const float* __restrict__ w) {
    int split = blockIdx.x;   // 0..7 (88 ci each)
    int cog   = blockIdx.y;   // 0..1 (32 couts each)
    int b     = blockIdx.z;
    __shared__ __align__(16) float tile[532];
    __shared__ __align__(16) float ws[288];          // [k][j], j = co_local 0..31
    int t = threadIdx.x;
    int oh = t / 21, ow = t % 21;
    bool active = (t < 441);
    u64 acc[16];
#pragma unroll
    for (int i = 0; i < 16; i++) acc[i] = 0ull;
    int ci0 = split*88;
    for (int ci = ci0; ci < ci0 + 88; ci++) {
        __syncthreads();
        for (int i = t; i < 529; i += 448)
            tile[i] = g_h[((size_t)(b*704 + ci))*529 + i];
        if (t < 288) {
            int j = t / 9, k = t % 9;
            ws[k*32 + j] = w[((size_t)(cog*32 + j)*704 + ci)*9 + k];
        }
        __syncthreads();
        if (active) {
            float r[9];
#pragma unroll
            for (int kh = 0; kh < 3; kh++)
#pragma unroll
                for (int kw = 0; kw < 3; kw++)
                    r[kh*3 + kw] = tile[(oh + kh)*23 + ow + kw];
#pragma unroll
            for (int k = 0; k < 9; k++) {
                u64 pv = pack2(r[k], r[k]);
                const ulonglong2* w2 = (const ulonglong2*)(ws + k*32);
#pragma unroll
                for (int g = 0; g < 8; g++) {
                    ulonglong2 q = w2[g];
                    acc[2*g  ] = ffma2(pv, q.x, acc[2*g  ]);
                    acc[2*g+1] = ffma2(pv, q.y, acc[2*g+1]);
                }
            }
        }
    }
    if (active) {
#pragma unroll
        for (int k = 0; k < 16; k++) {
            float lo, hi;
            unpack2(acc[k], lo, hi);
            int co = cog*32 + 2*k;
            g_c1p[(((size_t)split*16 + b)*64 + co    )*441 + t] = lo;
            g_c1p[(((size_t)split*16 + b)*64 + co + 1)*441 + t] = hi;
        }
    }
}

__global__ void conv1_reduce() {
    int o = blockIdx.x*256 + threadIdx.x;
    if (o >= 16*64*441) return;
    float s = 0.f;
#pragma unroll
    for (int k = 0; k < 8; k++) s += g_c1p[(size_t)k*16*64*441 + o];
    g_c1[o] = s;
}

// ---------------- bn1 stats ----------------
__global__ void bn1_stats(const float* __restrict__ g, const float* __restrict__ bb) {
    int c = blockIdx.x;
    float s = 0.f, q = 0.f;
    for (int i = threadIdx.x; i < 16*441; i += 256) {
        int b = i / 441, t = i % 441;
        float v = g_c1[((size_t)(b*64 + c))*441 + t];
        s += v; q += v*v;
    }
    __shared__ float rs[256], rq[256];
    rs[threadIdx.x] = s; rq[threadIdx.x] = q; __syncthreads();
    for (int st = 128; st > 0; st >>= 1) {
        if (threadIdx.x < st) { rs[threadIdx.x] += rs[threadIdx.x+st]; rq[threadIdx.x] += rq[threadIdx.x+st]; }
        __syncthreads();
    }
    if (threadIdx.x == 0) {
        const float inv = 1.f / 7056.f;
        float m = rs[0]*inv, var = rq[0]*inv - m*m;
        float sc = g[c] * rsqrtf(var + 1e-5f);
        g_scale1[c] = sc; g_shift1[c] = bb[c] - m*sc;
    }
}

// ---------------- bn1+relu+maxpool2x2 ----------------
__global__ void pool1() {
    int idx = blockIdx.x*256 + threadIdx.x;   // 16*64*100
    if (idx >= 102400) return;
    int ow = idx % 10, oh = (idx/10) % 10, c = (idx/100) % 64, b = idx/6400;
    float sc = g_scale1[c], sh = g_shift1[c];
    const float* src = g_c1 + ((size_t)(b*64 + c))*441;
    float m = 0.f;
#pragma unroll
    for (int dy = 0; dy < 2; dy++)
#pragma unroll
        for (int dx = 0; dx < 2; dx++)
            m = fmaxf(m, fmaxf(sc*src[(oh*2 + dy)*21 + ow*2 + dx] + sh, 0.f));
    g_p1[idx] = m;
}

// ---------------- conv2 3x3 valid, 64->32, +bias, relu ----------------
__global__ void conv2_kernel(const float* __restrict__ w, const float* __restrict__ bias) {
    int idx = blockIdx.x*256 + threadIdx.x;   // 16*32*64
    int ow = idx & 7, oh = (idx >> 3) & 7, co = (idx >> 6) & 31, b = idx >> 11;
    const float* src = g_p1 + (size_t)b*6400;
    const float* wp  = w + (size_t)co*576;
    float acc = bias[co];
    for (int ci = 0; ci < 64; ci++) {
        const float* sp = src + ci*100;
        const float* wc = wp + ci*9;
#pragma unroll
        for (int kh = 0; kh < 3; kh++)
#pragma unroll
            for (int kw = 0; kw < 3; kw++)
                acc += sp[(oh + kh)*10 + ow + kw] * wc[kh*3 + kw];
    }
    g_c2[idx] = fmaxf(acc, 0.f);
}

// ---------------- fc1 + relu ----------------
__global__ __launch_bounds__(128) void fc1_kernel(const float* __restrict__ w, const float* __restrict__ bias) {
    int b = blockIdx.x, j = threadIdx.x;
    __shared__ __align__(16) float xv[2048];
    for (int i = j; i < 2048; i += 128) xv[i] = g_c2[(size_t)b*2048 + i];
    __syncthreads();
    const float4* wp = (const float4*)(w + (size_t)j*2048);
    const float4* xp = (const float4*)xv;
    float acc = 0.f;
#pragma unroll 4
    for (int k = 0; k < 512; k++) {
        float4 wv = wp[k], x4 = xp[k];
        acc += wv.x*x4.x + wv.y*x4.y + wv.z*x4.z + wv.w*x4.w;
    }
    g_fc1[b*128 + j] = fmaxf(acc + bias[j], 0.f);
}

// ---------------- head + tanh ----------------
__global__ void head_kernel(const float* __restrict__ w, const float* __restrict__ bias,
                            float* __restrict__ out) {
    int t = threadIdx.x; if (t >= 192) return;
    int b = t / 12, j = t % 12;
    const float* wp = w + j*128;
    const float* xp = g_fc1 + b*128;
    float acc = bias[j];
#pragma unroll 4
    for (int k = 0; k < 128; k++) acc += wp[k]*xp[k];
    out[b*12 + j] = tanhf(acc);
}

// ---------------- launch ----------------
extern "C" void kernel_launch(void* const* d_in, const int* in_sizes, int n_in,
                              void* d_out, int out_size) {
    const float* x       = (const float*)d_in[0];
    const float* box     = (const float*)d_in[1];
    const float* stem_w  = (const float*)d_in[2];
    const float* stem_g  = (const float*)d_in[3];
    const float* stem_b  = (const float*)d_in[4];
    const float* conv1_w = (const float*)d_in[5];
    /* conv1_b (d_in[6]) cancels under batchnorm's mean subtraction */
    const float* bn1_g   = (const float*)d_in[7];
    const float* bn1_b   = (const float*)d_in[8];
    const float* conv2_w = (const float*)d_in[9];
    const float* conv2_b = (const float*)d_in[10];
    const float* fc1_w   = (const float*)d_in[11];
    const float* fc1_b   = (const float*)d_in[12];
    const float* head_w  = (const float*)d_in[13];
    const float* head_b  = (const float*)d_in[14];
    float* out = (float*)d_out;

    // 3 probes put stem_kernel in ncu's captured (4th) launch slot
    probe0<<<1, 32>>>();
    probe1<<<1, 32>>>();
    probe2<<<1, 32>>>();

    stem_kernel<<<dim3(256, 16), 256>>>(x, stem_w);
    bn0_final<<<64, 256>>>(stem_g, stem_b);
    pool0<<<32768, 256>>>();

    double a1 = -5.0*PI_D/180.0, a2 = 5.0*PI_D/180.0;
    gridsample_kernel<<<dim3(128, 16, 2), 128>>>(
        (float)cos(a1), (float)sin(-a1), 0.f, (float)sin(a1), (float)cos(a1), 0.f,
        (float)cos(a2), (float)sin(-a2), 0.f, (float)sin(a2), (float)cos(a2), 0.f);

    roialign_kernel<<<dim3(176, 4), 256>>>(box);

    conv1_kernel<<<dim3(8, 2, 16), 448>>>(conv1_w);
    conv1_reduce<<<1764, 256>>>();
    bn1_stats<<<64, 256>>>(bn1_g, bn1_b);
    pool1<<<400, 256>>>();
    conv2_kernel<<<128, 256>>>(conv2_w, conv2_b);
    fc1_kernel<<<16, 128>>>(fc1_w, fc1_b);
    head_kernel<<<1, 256>>>(head_w, head_b, out);
}

// round 10
// speedup vs baseline: 1.1062x; 1.0988x over previous
#include <cuda_runtime.h>
#include <math.h>

// ---------------- constants ----------------
#define NB 16
#define C1 64
#define H1 256
#define HP 128
#define CH 704
#define NP 23
#define PI_D 3.14159265358979323846

typedef unsigned long long u64;

// packed fp32x2 helpers (SASS FFMA2 — 2x fp32 FMA per issue, IEEE-exact per lane)
__device__ __forceinline__ u64 ffma2(u64 a, u64 b, u64 c) {
    u64 d;
    asm("fma.rn.f32x2 %0, %1, %2, %3;" : "=l"(d) : "l"(a), "l"(b), "l"(c));
    return d;
}
__device__ __forceinline__ u64 pack2(float x, float y) {
    u64 d;
    asm("mov.b64 %0, {%1, %2};" : "=l"(d) : "f"(x), "f"(y));
    return d;
}
__device__ __forceinline__ void unpack2(u64 v, float& x, float& y) {
    asm("mov.b64 {%0, %1}, %2;" : "=f"(x), "=f"(y) : "l"(v));
}

// ---------------- device scratch ----------------
__device__ float g_conv0[(size_t)NB*C1*H1*H1];       // 256 MB
__device__ float g_f   [(size_t)NB*C1*HP*HP];        // 64 MB
__device__ float g_xt1 [(size_t)NB*C1*HP*HP];
__device__ float g_xt2 [(size_t)NB*C1*HP*HP];
__device__ float g_h   [(size_t)NB*CH*NP*NP];
__device__ float g_c1p [(size_t)8*NB*64*441];
__device__ float g_c1  [(size_t)NB*64*441];
__device__ float g_p1  [(size_t)NB*64*100];
__device__ float g_c2  [(size_t)NB*32*64];
__device__ float g_fc1 [(size_t)NB*128];
__device__ float g_bn0row[2*64*4096];                // [sum/sq][ch][block]
__device__ float g_scale0[64], g_shift0[64];
__device__ float g_scale1[64], g_shift1[64];
__device__ float g_probe[4];

// ---------------- probe kernels (shift stem into ncu's 4th-launch capture slot) ----------------
__global__ void probe0() { if (threadIdx.x == 0) g_probe[0] = 0.f; }
__global__ void probe1() { if (threadIdx.x == 0) g_probe[1] = 0.f; }
__global__ void probe2() { if (threadIdx.x == 0) g_probe[2] = 0.f; }

// ---------------- stem conv: 7x7 s2 p3, 3->64 ch, FFMA2 ----------------
// block = one output row (256 px), 256 threads, dynamic smem:
//   ws[9408]  : weights [idx][64], idx = c*49+kh*7+kw
//   sin[3*7*532]: input rows de-interleaved [c][kh][iw+4], zero-padded borders
// thread: q = t>>6 -> channels [16q,16q+16); tt = t&63 -> pixels 4tt..4tt+3.
// Per (c,kh): 16-float register cache of the input row segment; all 7x4 taps
// read from registers. Weights: 4 LDS.128 (broadcast) per tap.
// Emits per-block bn partials (deterministic).
#define STEM_SMEM_FLOATS (9408 + 3*7*532)
__global__ __launch_bounds__(256) void stem_kernel(const float* __restrict__ x,
                                                   const float* __restrict__ w) {
    extern __shared__ float sm[];
    float* ws  = sm;            // 9408 floats
    float* sin = sm + 9408;     // 11172 floats
    int b = blockIdx.y, oh = blockIdx.x;
    int t = threadIdx.x;
    // weights [idx][64]
    for (int i = t; i < 9408; i += 256) {
        int co = i / 147, idx = i % 147;
        ws[idx*64 + co] = w[i];
    }
    // stage input rows, de-interleaved + zero borders
    for (int i = t; i < 3*7*532; i += 256) {
        int c = i / 3724, rem = i - c*3724;
        int kh = rem / 532, pos = rem - kh*532;
        int iw = pos - 4;
        int ih = oh*2 - 3 + kh;
        float v = 0.f;
        if ((unsigned)ih < 512u && (unsigned)iw < 512u)
            v = x[(((size_t)b*512 + ih)*512 + iw)*3 + c];
        sin[i] = v;
    }
    __syncthreads();
    int q = t >> 6, tt = t & 63;
    u64 acc[4][8];                       // [pixel][chan pair]
#pragma unroll
    for (int p = 0; p < 4; p++)
#pragma unroll
        for (int k = 0; k < 8; k++) acc[p][k] = 0ull;
#pragma unroll 1
    for (int c = 0; c < 3; c++) {
#pragma unroll 1
        for (int kh = 0; kh < 7; kh++) {
            const float* row = sin + (c*7 + kh)*532 + 8*tt;
            // register cache: slots [8tt, 8tt+16) -> iw [8tt-4, 8tt+12)
            float4 r0 = *(const float4*)(row);
            float4 r1 = *(const float4*)(row + 4);
            float4 r2 = *(const float4*)(row + 8);
            float4 r3 = *(const float4*)(row + 12);
            float rin[16] = {r0.x, r0.y, r0.z, r0.w, r1.x, r1.y, r1.z, r1.w,
                             r2.x, r2.y, r2.z, r2.w, r3.x, r3.y, r3.z, r3.w};
            int idx0 = (c*7 + kh)*7;
#pragma unroll
            for (int kw = 0; kw < 7; kw++) {
                // pixel p value: slot = 8tt + 1 + kw + 2p
                u64 pv0 = pack2(rin[1 + kw    ], rin[1 + kw    ]);
                u64 pv1 = pack2(rin[3 + kw    ], rin[3 + kw    ]);
                u64 pv2 = pack2(rin[5 + kw    ], rin[5 + kw    ]);
                u64 pv3 = pack2(rin[7 + kw    ], rin[7 + kw    ]);
                const ulonglong2* wp = (const ulonglong2*)(ws + (idx0 + kw)*64 + q*16);
                ulonglong2 qa = wp[0], qb = wp[1], qc = wp[2], qd = wp[3];
                acc[0][0] = ffma2(pv0, qa.x, acc[0][0]);
                acc[0][1] = ffma2(pv0, qa.y, acc[0][1]);
                acc[0][2] = ffma2(pv0, qb.x, acc[0][2]);
                acc[0][3] = ffma2(pv0, qb.y, acc[0][3]);
                acc[0][4] = ffma2(pv0, qc.x, acc[0][4]);
                acc[0][5] = ffma2(pv0, qc.y, acc[0][5]);
                acc[0][6] = ffma2(pv0, qd.x, acc[0][6]);
                acc[0][7] = ffma2(pv0, qd.y, acc[0][7]);
                acc[1][0] = ffma2(pv1, qa.x, acc[1][0]);
                acc[1][1] = ffma2(pv1, qa.y, acc[1][1]);
                acc[1][2] = ffma2(pv1, qb.x, acc[1][2]);
                acc[1][3] = ffma2(pv1, qb.y, acc[1][3]);
                acc[1][4] = ffma2(pv1, qc.x, acc[1][4]);
                acc[1][5] = ffma2(pv1, qc.y, acc[1][5]);
                acc[1][6] = ffma2(pv1, qd.x, acc[1][6]);
                acc[1][7] = ffma2(pv1, qd.y, acc[1][7]);
                acc[2][0] = ffma2(pv2, qa.x, acc[2][0]);
                acc[2][1] = ffma2(pv2, qa.y, acc[2][1]);
                acc[2][2] = ffma2(pv2, qb.x, acc[2][2]);
                acc[2][3] = ffma2(pv2, qb.y, acc[2][3]);
                acc[2][4] = ffma2(pv2, qc.x, acc[2][4]);
                acc[2][5] = ffma2(pv2, qc.y, acc[2][5]);
                acc[2][6] = ffma2(pv2, qd.x, acc[2][6]);
                acc[2][7] = ffma2(pv2, qd.y, acc[2][7]);
                acc[3][0] = ffma2(pv3, qa.x, acc[3][0]);
                acc[3][1] = ffma2(pv3, qa.y, acc[3][1]);
                acc[3][2] = ffma2(pv3, qb.x, acc[3][2]);
                acc[3][3] = ffma2(pv3, qb.y, acc[3][3]);
                acc[3][4] = ffma2(pv3, qc.x, acc[3][4]);
                acc[3][5] = ffma2(pv3, qc.y, acc[3][5]);
                acc[3][6] = ffma2(pv3, qd.x, acc[3][6]);
                acc[3][7] = ffma2(pv3, qd.y, acc[3][7]);
            }
        }
    }
    // store: per channel float4 (4 consecutive pixels) — fully coalesced
    size_t base = ((size_t)(b*64 + q*16))*65536 + (size_t)oh*256 + 4*tt;
#pragma unroll
    for (int k = 0; k < 8; k++) {
        float l0, h0, l1, h1, l2, h2, l3, h3;
        unpack2(acc[0][k], l0, h0);
        unpack2(acc[1][k], l1, h1);
        unpack2(acc[2][k], l2, h2);
        unpack2(acc[3][k], l3, h3);
        *(float4*)(g_conv0 + base + (size_t)(2*k  )*65536) = make_float4(l0, l1, l2, l3);
        *(float4*)(g_conv0 + base + (size_t)(2*k+1)*65536) = make_float4(h0, h1, h2, h3);
    }
    // ---- bn partial stats over this row (deterministic) ----
    int blk = b*256 + oh;
    float* red = sm;                     // [64][65], reuses weight area
    int rc = t >> 2, rq = t & 3;
    // pass 1: sums
    __syncthreads();
#pragma unroll
    for (int k = 0; k < 8; k++) {
        float l0, h0, l1, h1, l2, h2, l3, h3;
        unpack2(acc[0][k], l0, h0);
        unpack2(acc[1][k], l1, h1);
        unpack2(acc[2][k], l2, h2);
        unpack2(acc[3][k], l3, h3);
        red[(q*16 + 2*k  )*65 + tt] = (l0 + l1) + (l2 + l3);
        red[(q*16 + 2*k+1)*65 + tt] = (h0 + h1) + (h2 + h3);
    }
    __syncthreads();
    {
        float s = 0.f;
#pragma unroll
        for (int i = 0; i < 16; i++) s += red[rc*65 + rq*16 + i];
        s += __shfl_xor_sync(0xffffffffu, s, 1);
        s += __shfl_xor_sync(0xffffffffu, s, 2);
        if (rq == 0) g_bn0row[rc*4096 + blk] = s;
    }
    __syncthreads();
    // pass 2: sums of squares
#pragma unroll
    for (int k = 0; k < 8; k++) {
        float l0, h0, l1, h1, l2, h2, l3, h3;
        unpack2(acc[0][k], l0, h0);
        unpack2(acc[1][k], l1, h1);
        unpack2(acc[2][k], l2, h2);
        unpack2(acc[3][k], l3, h3);
        red[(q*16 + 2*k  )*65 + tt] = (l0*l0 + l1*l1) + (l2*l2 + l3*l3);
        red[(q*16 + 2*k+1)*65 + tt] = (h0*h0 + h1*h1) + (h2*h2 + h3*h3);
    }
    __syncthreads();
    {
        float s = 0.f;
#pragma unroll
        for (int i = 0; i < 16; i++) s += red[rc*65 + rq*16 + i];
        s += __shfl_xor_sync(0xffffffffu, s, 1);
        s += __shfl_xor_sync(0xffffffffu, s, 2);
        if (rq == 0) g_bn0row[(64 + rc)*4096 + blk] = s;
    }
}

// ---------------- bn0 final: reduce 4096 row-partials per channel ----------------
__global__ void bn0_final(const float* __restrict__ g, const float* __restrict__ bb) {
    int c = blockIdx.x;
    float s = 0.f, q = 0.f;
    for (int i = threadIdx.x; i < 4096; i += 256) {
        s += g_bn0row[c*4096 + i];
        q += g_bn0row[(64 + c)*4096 + i];
    }
    __shared__ float rs[256], rq[256];
    rs[threadIdx.x] = s; rq[threadIdx.x] = q; __syncthreads();
    for (int st = 128; st > 0; st >>= 1) {
        if (threadIdx.x < st) { rs[threadIdx.x] += rs[threadIdx.x+st]; rq[threadIdx.x] += rq[threadIdx.x+st]; }
        __syncthreads();
    }
    if (threadIdx.x == 0) {
        const float inv = 1.f / 1048576.f;
        float m = rs[0]*inv, var = rq[0]*inv - m*m;
        float sc = g[c] * rsqrtf(var + 1e-5f);
        g_scale0[c] = sc; g_shift0[c] = bb[c] - m*sc;
    }
}

// ---------------- fused bn+relu+maxpool 3x3 s2 p1, 2 outputs/thread ----------------
__global__ void pool0() {
    int idx = blockIdx.x*256 + threadIdx.x;          // 16*64*128*64
    int owp = idx & 63, oh = (idx >> 6) & 127, c = (idx >> 13) & 63, b = idx >> 19;
    float sc = g_scale0[c], sh = g_shift0[c];
    const float* src = g_conv0 + ((size_t)(b*64 + c))*65536;
    float mx0 = -3.4e38f, mn0 = 3.4e38f, mx1 = -3.4e38f, mn1 = 3.4e38f;
    int c0 = 4*owp;
#pragma unroll
    for (int dy = 0; dy < 3; dy++) {
        int ih = oh*2 - 1 + dy;
        if ((unsigned)ih >= 256u) continue;
        const float* r = src + ih*256;
        float4 qv = *(const float4*)(r + c0);
        if (owp > 0) {
            float left = r[c0 - 1];
            mx0 = fmaxf(mx0, left); mn0 = fminf(mn0, left);
        }
        mx0 = fmaxf(mx0, fmaxf(qv.x, qv.y));
        mn0 = fminf(mn0, fminf(qv.x, qv.y));
        mx1 = fmaxf(mx1, fmaxf(qv.y, fmaxf(qv.z, qv.w)));
        mn1 = fminf(mn1, fminf(qv.y, fminf(qv.z, qv.w)));
    }
    float v0 = (sc >= 0.f) ? sc*mx0 + sh : sc*mn0 + sh;
    float v1 = (sc >= 0.f) ? sc*mx1 + sh : sc*mn1 + sh;
    size_t obase = ((size_t)(b*64 + c))*16384 + (size_t)oh*128 + 2*owp;
    *(float2*)(g_f + obase) = make_float2(fmaxf(v0, 0.f), fmaxf(v1, 0.f));
}

// ---------------- grid_sample, both thetas in one launch (proven 1 px/thread) ----------------
__global__ void gridsample_kernel(float p00, float p01, float p02,
                                  float p10, float p11, float p12,
                                  float q00, float q01, float q02,
                                  float q10, float q11, float q12) {
    int w = threadIdx.x, hh = blockIdx.x, b = blockIdx.y, which = blockIdx.z;
    float t00 = which ? q00 : p00, t01 = which ? q01 : p01, t02 = which ? q02 : p02;
    float t10 = which ? q10 : p10, t11 = which ? q11 : p11, t12 = which ? q12 : p12;
    float* out = which ? g_xt2 : g_xt1;
    float gx = (float)(2*w + 1) * (1.f/128.f) - 1.f;
    float gy = (float)(2*hh + 1) * (1.f/128.f) - 1.f;
    float grx = gx*t00 + gy*t01 + t02;
    float gry = gx*t10 + gy*t11 + t12;
    float ix = ((grx + 1.f)*128.f - 1.f)*0.5f;
    float iy = ((gry + 1.f)*128.f - 1.f)*0.5f;
    float x0f = floorf(ix), y0f = floorf(iy);
    int x0 = (int)x0f, y0 = (int)y0f;
    float wa = (x0f + 1.f - ix)*(y0f + 1.f - iy);
    float wb = (x0f + 1.f - ix)*(iy - y0f);
    float wc = (ix - x0f)*(y0f + 1.f - iy);
    float wd = (ix - x0f)*(iy - y0f);
    int   off[4]; float wf[4];
    float wt[4] = {wa, wb, wc, wd};
    int xs2[2] = {x0, x0 + 1}, ys2[2] = {y0, y0 + 1};
#pragma unroll
    for (int dx = 0; dx < 2; dx++)
#pragma unroll
        for (int dy = 0; dy < 2; dy++) {
            int xx = xs2[dx], yy = ys2[dy];
            bool valid = ((unsigned)xx < 128u) && ((unsigned)yy < 128u);
            int xc = min(max(xx, 0), 127), yc = min(max(yy, 0), 127);
            int k = dx*2 + dy;
            off[k] = yc*128 + xc;
            wf[k] = valid ? wt[k] : 0.f;
        }
    size_t base = ((size_t)b*64)*16384;
    int pix = hh*128 + w;
    const float* src = g_f + base;
    for (int c = 0; c < 64; c++) {
        const float* sp = src + c*16384;
        out[base + (size_t)c*16384 + pix] =
            sp[off[0]]*wf[0] + sp[off[1]]*wf[1] + sp[off[2]]*wf[2] + sp[off[3]]*wf[3];
    }
}

// ---------------- roialign: 4-way channel split, writes into concat g_h ----------------
__global__ void roialign_kernel(const float* __restrict__ box) {
    int blk = blockIdx.x;            // 16*11
    int cq  = blockIdx.y;            // 0..3 -> channels [16cq, 16cq+16)
    int b = blk / 11, s = blk % 11;
    const float* feat; int r;
    if (s < 7)       { feat = g_f;   r = s;     }
    else if (s < 9)  { feat = g_xt1; r = s - 7; }
    else             { feat = g_xt2; r = s - 9; }
    const float* bx = box + b*28 + r*4;
    float rx1 = bx[0]*0.25f, ry1 = bx[1]*0.25f, rx2 = bx[2]*0.25f, ry2 = bx[3]*0.25f;
    float bw = fmaxf(rx2 - rx1, 1.f) * (1.f/23.f);
    float bh = fmaxf(ry2 - ry1, 1.f) * (1.f/23.f);
    __shared__ int   sy0[46], sy1[46], sx0[46], sx1[46];
    __shared__ float sly[46], slx[46];
    __shared__ int   sey[46], sex[46];
    int t = threadIdx.x;
    if (t < 46) {
        float pos = (float)(t >> 1) + 0.25f + 0.5f*(float)(t & 1);
        float yv = ry1 + pos*bh;
        sey[t] = (yv < -1.f) || (yv > 128.f);
        float y = fminf(fmaxf(yv, 0.f), 127.f);
        float y0f = floorf(y); int y0 = (int)y0f;
        sy0[t] = y0; sy1[t] = min(y0 + 1, 127); sly[t] = y - y0f;
        float xv = rx1 + pos*bw;
        sex[t] = (xv < -1.f) || (xv > 128.f);
        float xx = fminf(fmaxf(xv, 0.f), 127.f);
        float x0f = floorf(xx); int x0 = (int)x0f;
        sx0[t] = x0; sx1[t] = min(x0 + 1, 127); slx[t] = xx - x0f;
    }
    __syncthreads();
    const float* fb = feat + ((size_t)b*64)*16384;
    float* ob = g_h + ((size_t)(b*704 + s*64))*529;
    for (int o = t; o < 16*529; o += 256) {
        int c = cq*16 + o / 529, pp = o % 529;
        int py = pp / 23, px = pp % 23;
        const float* img = fb + (size_t)c*16384;
        float acc = 0.f;
#pragma unroll
        for (int dy = 0; dy < 2; dy++) {
            int jy = py*2 + dy;
            int yy0 = sy0[jy], yy1 = sy1[jy];
            float ly = sly[jy], hy = 1.f - ly;
            int ey = sey[jy];
#pragma unroll
            for (int dx = 0; dx < 2; dx++) {
                int jx = px*2 + dx;
                int xx0 = sx0[jx], xx1 = sx1[jx];
                float lx = slx[jx], hx = 1.f - lx;
                float v = img[yy0*128 + xx0]*(hy*hx) + img[yy0*128 + xx1]*(hy*lx)
                        + img[yy1*128 + xx0]*(ly*hx) + img[yy1*128 + xx1]*(ly*lx);
                if (ey || sex[jx]) v = 0.f;
                acc += v;
            }
        }
        ob[(size_t)c*529 + pp] = acc * 0.25f;
    }
}

// ---------------- conv1 3x3 valid, 704->64, FFMA2, ci-split partials (proven) ----------------
__global__ __launch_bounds__(448) void conv1_kernel(const float* __restrict__ w) {
    int split = blockIdx.x;   // 0..7 (88 ci each)
    int cog   = blockIdx.y;   // 0..1 (32 couts each)
    int b     = blockIdx.z;
    __shared__ __align__(16) float tile[532];
    __shared__ __align__(16) float ws[288];          // [k][j], j = co_local 0..31
    int t = threadIdx.x;
    int oh = t / 21, ow = t % 21;
    bool active = (t < 441);
    u64 acc[16];
#pragma unroll
    for (int i = 0; i < 16; i++) acc[i] = 0ull;
    int ci0 = split*88;
    for (int ci = ci0; ci < ci0 + 88; ci++) {
        __syncthreads();
        for (int i = t; i < 529; i += 448)
            tile[i] = g_h[((size_t)(b*704 + ci))*529 + i];
        if (t < 288) {
            int j = t / 9, k = t % 9;
            ws[k*32 + j] = w[((size_t)(cog*32 + j)*704 + ci)*9 + k];
        }
        __syncthreads();
        if (active) {
            float r[9];
#pragma unroll
            for (int kh = 0; kh < 3; kh++)
#pragma unroll
                for (int kw = 0; kw < 3; kw++)
                    r[kh*3 + kw] = tile[(oh + kh)*23 + ow + kw];
#pragma unroll
            for (int k = 0; k < 9; k++) {
                u64 pv = pack2(r[k], r[k]);
                const ulonglong2* w2 = (const ulonglong2*)(ws + k*32);
#pragma unroll
                for (int g = 0; g < 8; g++) {
                    ulonglong2 q = w2[g];
                    acc[2*g  ] = ffma2(pv, q.x, acc[2*g  ]);
                    acc[2*g+1] = ffma2(pv, q.y, acc[2*g+1]);
                }
            }
        }
    }
    if (active) {
#pragma unroll
        for (int k = 0; k < 16; k++) {
            float lo, hi;
            unpack2(acc[k], lo, hi);
            int co = cog*32 + 2*k;
            g_c1p[(((size_t)split*16 + b)*64 + co    )*441 + t] = lo;
            g_c1p[(((size_t)split*16 + b)*64 + co + 1)*441 + t] = hi;
        }
    }
}

__global__ void conv1_reduce() {
    int o = blockIdx.x*256 + threadIdx.x;
    if (o >= 16*64*441) return;
    float s = 0.f;
#pragma unroll
    for (int k = 0; k < 8; k++) s += g_c1p[(size_t)k*16*64*441 + o];
    g_c1[o] = s;
}

// ---------------- bn1 stats ----------------
__global__ void bn1_stats(const float* __restrict__ g, const float* __restrict__ bb) {
    int c = blockIdx.x;
    float s = 0.f, q = 0.f;
    for (int i = threadIdx.x; i < 16*441; i += 256) {
        int b = i / 441, t = i % 441;
        float v = g_c1[((size_t)(b*64 + c))*441 + t];
        s += v; q += v*v;
    }
    __shared__ float rs[256], rq[256];
    rs[threadIdx.x] = s; rq[threadIdx.x] = q; __syncthreads();
    for (int st = 128; st > 0; st >>= 1) {
        if (threadIdx.x < st) { rs[threadIdx.x] += rs[threadIdx.x+st]; rq[threadIdx.x] += rq[threadIdx.x+st]; }
        __syncthreads();
    }
    if (threadIdx.x == 0) {
        const float inv = 1.f / 7056.f;
        float m = rs[0]*inv, var = rq[0]*inv - m*m;
        float sc = g[c] * rsqrtf(var + 1e-5f);
        g_scale1[c] = sc; g_shift1[c] = bb[c] - m*sc;
    }
}

// ---------------- bn1+relu+maxpool2x2 ----------------
__global__ void pool1() {
    int idx = blockIdx.x*256 + threadIdx.x;   // 16*64*100
    if (idx >= 102400) return;
    int ow = idx % 10, oh = (idx/10) % 10, c = (idx/100) % 64, b = idx/6400;
    float sc = g_scale1[c], sh = g_shift1[c];
    const float* src = g_c1 + ((size_t)(b*64 + c))*441;
    float m = 0.f;
#pragma unroll
    for (int dy = 0; dy < 2; dy++)
#pragma unroll
        for (int dx = 0; dx < 2; dx++)
            m = fmaxf(m, fmaxf(sc*src[(oh*2 + dy)*21 + ow*2 + dx] + sh, 0.f));
    g_p1[idx] = m;
}

// ---------------- conv2 3x3 valid, 64->32, +bias, relu ----------------
__global__ void conv2_kernel(const float* __restrict__ w, const float* __restrict__ bias) {
    int idx = blockIdx.x*256 + threadIdx.x;   // 16*32*64
    int ow = idx & 7, oh = (idx >> 3) & 7, co = (idx >> 6) & 31, b = idx >> 11;
    const float* src = g_p1 + (size_t)b*6400;
    const float* wp  = w + (size_t)co*576;
    float acc = bias[co];
    for (int ci = 0; ci < 64; ci++) {
        const float* sp = src + ci*100;
        const float* wc = wp + ci*9;
#pragma unroll
        for (int kh = 0; kh < 3; kh++)
#pragma unroll
            for (int kw = 0; kw < 3; kw++)
                acc += sp[(oh + kh)*10 + ow + kw] * wc[kh*3 + kw];
    }
    g_c2[idx] = fmaxf(acc, 0.f);
}

// ---------------- fc1 + relu ----------------
__global__ __launch_bounds__(128) void fc1_kernel(const float* __restrict__ w, const float* __restrict__ bias) {
    int b = blockIdx.x, j = threadIdx.x;
    __shared__ __align__(16) float xv[2048];
    for (int i = j; i < 2048; i += 128) xv[i] = g_c2[(size_t)b*2048 + i];
    __syncthreads();
    const float4* wp = (const float4*)(w + (size_t)j*2048);
    const float4* xp = (const float4*)xv;
    float acc = 0.f;
#pragma unroll 4
    for (int k = 0; k < 512; k++) {
        float4 wv = wp[k], x4 = xp[k];
        acc += wv.x*x4.x + wv.y*x4.y + wv.z*x4.z + wv.w*x4.w;
    }
    g_fc1[b*128 + j] = fmaxf(acc + bias[j], 0.f);
}

// ---------------- head + tanh ----------------
__global__ void head_kernel(const float* __restrict__ w, const float* __restrict__ bias,
                            float* __restrict__ out) {
    int t = threadIdx.x; if (t >= 192) return;
    int b = t / 12, j = t % 12;
    const float* wp = w + j*128;
    const float* xp = g_fc1 + b*128;
    float acc = bias[j];
#pragma unroll 4
    for (int k = 0; k < 128; k++) acc += wp[k]*xp[k];
    out[b*12 + j] = tanhf(acc);
}

// ---------------- launch ----------------
extern "C" void kernel_launch(void* const* d_in, const int* in_sizes, int n_in,
                              void* d_out, int out_size) {
    const float* x       = (const float*)d_in[0];
    const float* box     = (const float*)d_in[1];
    const float* stem_w  = (const float*)d_in[2];
    const float* stem_g  = (const float*)d_in[3];
    const float* stem_b  = (const float*)d_in[4];
    const float* conv1_w = (const float*)d_in[5];
    /* conv1_b (d_in[6]) cancels under batchnorm's mean subtraction */
    const float* bn1_g   = (const float*)d_in[7];
    const float* bn1_b   = (const float*)d_in[8];
    const float* conv2_w = (const float*)d_in[9];
    const float* conv2_b = (const float*)d_in[10];
    const float* fc1_w   = (const float*)d_in[11];
    const float* fc1_b   = (const float*)d_in[12];
    const float* head_w  = (const float*)d_in[13];
    const float* head_b  = (const float*)d_in[14];
    float* out = (float*)d_out;

    // opt-in to >48KB dynamic smem for the stem (idempotent, no allocation)
    static int smem_set = 0;
    if (!smem_set) {
        cudaFuncSetAttribute(stem_kernel, cudaFuncAttributeMaxDynamicSharedMemorySize,
                             STEM_SMEM_FLOATS*4);
        smem_set = 1;
    }

    // 3 probes put stem_kernel in ncu's captured (4th) launch slot
    probe0<<<1, 32>>>();
    probe1<<<1, 32>>>();
    probe2<<<1, 32>>>();

    stem_kernel<<<dim3(256, 16), 256, STEM_SMEM_FLOATS*4>>>(x, stem_w);
    bn0_final<<<64, 256>>>(stem_g, stem_b);
    pool0<<<32768, 256>>>();

    double a1 = -5.0*PI_D/180.0, a2 = 5.0*PI_D/180.0;
    gridsample_kernel<<<dim3(128, 16, 2), 128>>>(
        (float)cos(a1), (float)sin(-a1), 0.f, (float)sin(a1), (float)cos(a1), 0.f,
        (float)cos(a2), (float)sin(-a2), 0.f, (float)sin(a2), (float)cos(a2), 0.f);

    roialign_kernel<<<dim3(176, 4), 256>>>(box);

    conv1_kernel<<<dim3(8, 2, 16), 448>>>(conv1_w);
    conv1_reduce<<<1764, 256>>>();
    bn1_stats<<<64, 256>>>(bn1_g, bn1_b);
    pool1<<<400, 256>>>();
    conv2_kernel<<<128, 256>>>(conv2_w, conv2_b);
    fc1_kernel<<<16, 128>>>(fc1_w, fc1_b);
    head_kernel<<<1, 256>>>(head_w, head_b, out);
}